// round 16
// baseline (speedup 1.0000x reference)
#include <cuda_runtime.h>
#include <cuda_bf16.h>
#include <math.h>
#include <stdint.h>

#define BB   2
#define NQ   1024
#define NKK  2048
#define DIMN 1024
#define NH   16
#define HDIM 64

// ---------------- scratch (static device globals) ---------------------------
__device__ float g_qp[(size_t)BB * NH * NQ * HDIM];    // (B,H,NQ,HD), pre-scaled by 0.125
__device__ float g_kp[(size_t)BB * NH * NKK * HDIM];   // (B,H,NK,HD)
__device__ float g_vp[(size_t)BB * NH * NKK * HDIM];   // (B,H,NK,HD)
__device__ float g_gate[(size_t)BB * NQ * NKK];        // gate*valid, 0 if masked
__device__ float g_part[BB * 1024];
__device__ float g_coef[BB];
__device__ int   g_mask_mode;   // 0=uint8, 1=float32, 2=int32

// bf16 hi/lo planes for emulated-fp32 GEMMs
__device__ __align__(256) __nv_bfloat16 g_qh[(size_t)BB * NQ * DIMN];
__device__ __align__(256) __nv_bfloat16 g_ql[(size_t)BB * NQ * DIMN];
__device__ __align__(256) __nv_bfloat16 g_kh[(size_t)BB * NKK * DIMN];
__device__ __align__(256) __nv_bfloat16 g_kl[(size_t)BB * NKK * DIMN];
__device__ __align__(256) __nv_bfloat16 g_vh[(size_t)BB * NKK * DIMN];
__device__ __align__(256) __nv_bfloat16 g_vl[(size_t)BB * NKK * DIMN];
__device__ __align__(256) __nv_bfloat16 g_ah[(size_t)BB * NQ * DIMN];   // attn out hi
__device__ __align__(256) __nv_bfloat16 g_al[(size_t)BB * NQ * DIMN];   // attn out lo
__device__ __align__(256) __nv_bfloat16 g_wqh[(size_t)DIMN * DIMN];
__device__ __align__(256) __nv_bfloat16 g_wql[(size_t)DIMN * DIMN];
__device__ __align__(256) __nv_bfloat16 g_wkh[(size_t)DIMN * DIMN];
__device__ __align__(256) __nv_bfloat16 g_wkl[(size_t)DIMN * DIMN];
__device__ __align__(256) __nv_bfloat16 g_wvh[(size_t)DIMN * DIMN];
__device__ __align__(256) __nv_bfloat16 g_wvl[(size_t)DIMN * DIMN];
__device__ __align__(256) __nv_bfloat16 g_woh[(size_t)DIMN * DIMN];
__device__ __align__(256) __nv_bfloat16 g_wol[(size_t)DIMN * DIMN];

// ---------------- mask dtype detection -------------------------------------
__global__ void detect_kernel(const unsigned int* __restrict__ w) {
    __shared__ int hasF, le1;
    if (threadIdx.x == 0) { hasF = 0; le1 = 1; }
    __syncthreads();
    unsigned v = w[threadIdx.x];
    if (v == 0x3F800000u) atomicExch(&hasF, 1);
    if (v > 1u)           atomicExch(&le1, 0);
    __syncthreads();
    if (threadIdx.x == 0) g_mask_mode = hasF ? 1 : (le1 ? 2 : 0);
}

__device__ __forceinline__ bool mget(const void* p, size_t i, int mode) {
    if (mode == 1) return ((const float*)p)[i] != 0.0f;
    if (mode == 2) return ((const int*)p)[i] != 0;
    return ((const unsigned char*)p)[i] != 0;
}

// ---------------- mma helpers ------------------------------------------------
__device__ __forceinline__ unsigned f2tf(float f) {
    unsigned u;
    asm("cvt.rna.tf32.f32 %0, %1;" : "=r"(u) : "f"(f));
    return u;
}

__device__ __forceinline__ void mma_tf32(float* d, const unsigned* a, const unsigned* b) {
    asm volatile(
        "mma.sync.aligned.m16n8k8.row.col.f32.tf32.tf32.f32 "
        "{%0,%1,%2,%3}, {%4,%5,%6,%7}, {%8,%9}, {%0,%1,%2,%3};"
        : "+f"(d[0]), "+f"(d[1]), "+f"(d[2]), "+f"(d[3])
        : "r"(a[0]), "r"(a[1]), "r"(a[2]), "r"(a[3]), "r"(b[0]), "r"(b[1]));
}

__device__ __forceinline__ void mma_bf16(float* d, const unsigned* a, unsigned b0, unsigned b1) {
    asm volatile(
        "mma.sync.aligned.m16n8k16.row.col.f32.bf16.bf16.f32 "
        "{%0,%1,%2,%3}, {%4,%5,%6,%7}, {%8,%9}, {%0,%1,%2,%3};"
        : "+f"(d[0]), "+f"(d[1]), "+f"(d[2]), "+f"(d[3])
        : "r"(a[0]), "r"(a[1]), "r"(a[2]), "r"(a[3]), "r"(b0), "r"(b1));
}

// ---------------- fp32 -> bf16 hi/lo split (ALL inputs, one launch) ----------
__global__ void convert_all(const float* __restrict__ q, const float* __restrict__ k,
                            const float* __restrict__ v, const float* __restrict__ wq,
                            const float* __restrict__ wk, const float* __restrict__ wv,
                            const float* __restrict__ wo)
{
    int blk = blockIdx.x;
    const float* src; __nv_bfloat16 *hi, *lo; int lb;
    if (blk < 1024)      { src = q;  hi = g_qh;  lo = g_ql;  lb = blk; }
    else if (blk < 3072) { src = k;  hi = g_kh;  lo = g_kl;  lb = blk - 1024; }
    else if (blk < 5120) { src = v;  hi = g_vh;  lo = g_vl;  lb = blk - 3072; }
    else if (blk < 5632) { src = wq; hi = g_wqh; lo = g_wql; lb = blk - 5120; }
    else if (blk < 6144) { src = wk; hi = g_wkh; lo = g_wkl; lb = blk - 5632; }
    else if (blk < 6656) { src = wv; hi = g_wvh; lo = g_wvl; lb = blk - 6144; }
    else                 { src = wo; hi = g_woh; lo = g_wol; lb = blk - 6656; }

    int i0 = (lb * 256 + threadIdx.x) * 8;
    float4 va = *(const float4*)(src + i0);
    float4 vb = *(const float4*)(src + i0 + 4);
    float f[8] = {va.x, va.y, va.z, va.w, vb.x, vb.y, vb.z, vb.w};
    __nv_bfloat16 h[8], l[8];
#pragma unroll
    for (int u = 0; u < 8; u++) {
        h[u] = __float2bfloat16(f[u]);
        l[u] = __float2bfloat16(f[u] - __bfloat162float(h[u]));
    }
    *(uint4*)(hi + i0) = *(uint4*)h;
    *(uint4*)(lo + i0) = *(uint4*)l;
}

// ---------------- bf16x3 GEMM: C = A(MxK) @ W(NxK)^T, K=1024 ----------------
#define GK      32
#define GSTAGES 3
#define GPLANE  2048
#define GSTAGEU (4 * GPLANE)
#define GSMEMU  (GSTAGES * GSTAGEU)     // 96 KB

__device__ __forceinline__ int gsw(int r, int p) {
    return r * 16 + ((((p >> 2) ^ ((r >> 1) & 3))) << 2) + (p & 3);
}

__global__ void __launch_bounds__(256, 2) gemm_bf16x3(
    float* __restrict__ Cout, int aselp, const void* __restrict__ kpmq)
{
    extern __shared__ unsigned smu[];

    int by = blockIdx.y;
    int asel, row0, Nseq;
    if (aselp == -1) {
        if (by < 16)      { asel = 0; row0 = by * 128;        Nseq = NQ;  }
        else if (by < 48) { asel = 1; row0 = (by - 16) * 128; Nseq = NKK; }
        else              { asel = 2; row0 = (by - 48) * 128; Nseq = NKK; }
    } else { asel = 3; row0 = by * 128; Nseq = NQ; }

    const __nv_bfloat16 *Ah, *Al, *Bh, *Bl;
    switch (asel) {
        case 0: Ah = g_qh; Al = g_ql; Bh = g_wqh; Bl = g_wql; break;
        case 1: Ah = g_kh; Al = g_kl; Bh = g_wkh; Bl = g_wkl; break;
        case 2: Ah = g_vh; Al = g_vl; Bh = g_wvh; Bl = g_wvl; break;
        default: Ah = g_ah; Al = g_al; Bh = g_woh; Bl = g_wol; break;
    }

    int tid  = threadIdx.x;
    int lane = tid & 31;
    int warp = tid >> 5;
    int g    = lane >> 2;
    int t4   = lane & 3;
    int wm   = warp >> 2;
    int wn   = warp & 3;
    int col0 = blockIdx.x * 128;

    int rcA = tid;

    float acc[4][4][4];
#pragma unroll
    for (int i = 0; i < 4; i++)
#pragma unroll
        for (int j = 0; j < 4; j++)
#pragma unroll
            for (int c = 0; c < 4; c++) acc[i][j][c] = 0.0f;

    auto issue = [&](int stage, int k0) {
        unsigned sbase = (unsigned)__cvta_generic_to_shared(smu + stage * GSTAGEU);
#pragma unroll
        for (int i = 0; i < 8; i++) {
            const int m = i >> 1;
            int rc = (i & 1) * 256 + rcA;
            int r  = rc >> 2, c = rc & 3;
            const __nv_bfloat16* base =
                (m == 0) ? Ah : (m == 1) ? Al : (m == 2) ? Bh : Bl;
            int rb = (m < 2) ? row0 : col0;
            const __nv_bfloat16* src = base + (size_t)(rb + r) * DIMN + k0 + c * 8;
            unsigned dst = sbase +
                (unsigned)((m * GPLANE + r * 16 + ((c ^ ((r >> 1) & 3)) << 2)) * 4);
            asm volatile("cp.async.cg.shared.global [%0], [%1], 16;\n"
                         :: "r"(dst), "l"(src));
        }
        asm volatile("cp.async.commit_group;\n" ::: "memory");
    };

    issue(0, 0);
    issue(1, GK);

    const int NIT = DIMN / GK;
    for (int it = 0; it < NIT; ++it) {
        asm volatile("cp.async.wait_group 1;\n" ::: "memory");
        __syncthreads();
        if (it + 2 < NIT) issue((it + 2) % GSTAGES, (it + 2) * GK);
        else asm volatile("cp.async.commit_group;\n" ::: "memory");

        const unsigned* sAh = smu + (it % GSTAGES) * GSTAGEU;
        const unsigned* sAl = sAh + GPLANE;
        const unsigned* sBh = sAl + GPLANE;
        const unsigned* sBl = sBh + GPLANE;

#pragma unroll
        for (int g16 = 0; g16 < 2; g16++) {
            int p0 = g16 * 8 + t4;
            unsigned bh[4][2], bl[4][2];
#pragma unroll
            for (int nj = 0; nj < 4; nj++) {
                int Cr = wn * 32 + nj * 8 + g;
                bh[nj][0] = sBh[gsw(Cr, p0)];
                bh[nj][1] = sBh[gsw(Cr, p0 + 4)];
                bl[nj][0] = sBl[gsw(Cr, p0)];
                bl[nj][1] = sBl[gsw(Cr, p0 + 4)];
            }
#pragma unroll
            for (int mi = 0; mi < 4; mi++) {
                int Rb = wm * 64 + mi * 16;
                unsigned ah[4], al[4];
                ah[0] = sAh[gsw(Rb + g,     p0)];
                ah[1] = sAh[gsw(Rb + g + 8, p0)];
                ah[2] = sAh[gsw(Rb + g,     p0 + 4)];
                ah[3] = sAh[gsw(Rb + g + 8, p0 + 4)];
                al[0] = sAl[gsw(Rb + g,     p0)];
                al[1] = sAl[gsw(Rb + g + 8, p0)];
                al[2] = sAl[gsw(Rb + g,     p0 + 4)];
                al[3] = sAl[gsw(Rb + g + 8, p0 + 4)];
#pragma unroll
                for (int nj = 0; nj < 4; nj++) {
                    mma_bf16(acc[mi][nj], ah, bh[nj][0], bh[nj][1]);
                    mma_bf16(acc[mi][nj], ah, bl[nj][0], bl[nj][1]);
                    mma_bf16(acc[mi][nj], al, bh[nj][0], bh[nj][1]);
                }
            }
        }
    }

    int mode = g_mask_mode;
#pragma unroll
    for (int mi = 0; mi < 4; mi++) {
#pragma unroll
        for (int h2 = 0; h2 < 2; h2++) {
            int r = row0 + wm * 64 + mi * 16 + g + 8 * h2;
            float rowscale = 1.0f;
            if (asel == 3) rowscale = mget(kpmq, (size_t)r, mode) ? 1.0f : 0.0f;
#pragma unroll
            for (int nj = 0; nj < 4; nj++) {
                int c = col0 + wn * 32 + nj * 8 + 2 * t4;
                float v0 = acc[mi][nj][2 * h2];
                float v1 = acc[mi][nj][2 * h2 + 1];
                if (asel == 0) { v0 *= 0.125f; v1 *= 0.125f; }
                if (asel == 3) {
                    Cout[(size_t)r * DIMN + c]     = v0 * rowscale;
                    Cout[(size_t)r * DIMN + c + 1] = v1 * rowscale;
                } else {
                    float* dst = (asel == 0) ? g_qp : ((asel == 1) ? g_kp : g_vp);
                    int bb = r / Nseq, ns = r - bb * Nseq;
                    int hh = c >> 6, hd = c & 63;
                    float* dp = dst + (((size_t)bb * NH + hh) * Nseq + ns) * HDIM + hd;
                    dp[0] = v0; dp[1] = v1;
                }
            }
        }
    }
}

// ---------------- distance mean -> gate coefficient -------------------------
// stage1: contiguous 8-float segments per thread, MLP>=4
__global__ void mean_stage1(const float* __restrict__ dist,
                            const void* __restrict__ am,
                            const void* __restrict__ kpmk)
{
    int mode = g_mask_mode;
    int b = blockIdx.y;
    size_t base = (size_t)b * NQ * NKK;
    int i0 = (blockIdx.x * 256 + threadIdx.x) * 8;   // within batch, 8 contiguous

    float4 d0 = *(const float4*)(dist + base + i0);
    float4 d1 = *(const float4*)(dist + base + i0 + 4);
    float dv[8] = {d0.x, d0.y, d0.z, d0.w, d1.x, d1.y, d1.z, d1.w};
    float s = 0.0f;
    int c0 = i0 & (NKK - 1);
#pragma unroll
    for (int u = 0; u < 8; u++) {
        if (mget(am, base + i0 + u, mode) && mget(kpmk, (size_t)b * NKK + c0 + u, mode))
            s += dv[u];
    }
    __shared__ float red[256];
    red[threadIdx.x] = s;
    __syncthreads();
    for (int st = 128; st > 0; st >>= 1) {
        if (threadIdx.x < st) red[threadIdx.x] += red[threadIdx.x + st];
        __syncthreads();
    }
    if (threadIdx.x == 0) g_part[b * 1024 + blockIdx.x] = red[0];
}

__global__ void mean_stage2(const float* __restrict__ galpha)
{
    int b = blockIdx.x;
    float s = 0.0f;
#pragma unroll
    for (int j = 0; j < 4; j++) s += g_part[b * 1024 + threadIdx.x + j * 256];
    __shared__ float red[256];
    red[threadIdx.x] = s;
    __syncthreads();
    for (int st = 128; st > 0; st >>= 1) {
        if (threadIdx.x < st) red[threadIdx.x] += red[threadIdx.x + st];
        __syncthreads();
    }
    if (threadIdx.x == 0) {
        float mean = red[0] / ((float)NQ * (float)NKK + 1e-6f);
        mean = fmaxf(mean, 1e-6f);
        float a = galpha[0];
        float alpha = log1pf(__expf(a));   // softplus
        g_coef[b] = alpha / mean;
    }
}

// ---------------- precompute gate*valid ------------------------------------
__global__ void gate_kernel(const float* __restrict__ dist,
                            const void* __restrict__ am,
                            const void* __restrict__ kpmk)
{
    int mode = g_mask_mode;
    size_t i0 = ((size_t)blockIdx.x * 256 + threadIdx.x) * 4;
    const size_t per_b = (size_t)NQ * NKK;
#pragma unroll
    for (int u = 0; u < 4; u++) {
        size_t i = i0 + u;
        int b = (int)(i / per_b);
        size_t rem = i - (size_t)b * per_b;
        int kk = (int)(rem & (NKK - 1));
        bool valid = mget(am, i, mode) && mget(kpmk, (size_t)b * NKK + kk, mode);
        g_gate[i] = valid ? __expf(-g_coef[b] * dist[i]) : 0.0f;
    }
}

// ---------------- fused flash attention (tf32 mma) --------------------------
// block: 128 thr = 4 warps; q-tile 64; k-tile 64; Q fragments in registers;
// smem only K/V/P -> 52 KB -> 3 CTAs/SM.
#define KS_STRIDE 68
#define VS_STRIDE 72
#define PS_STRIDE 68
#define ATTN_SMEM_UINTS (64*KS_STRIDE + 64*VS_STRIDE + 64*PS_STRIDE)

__device__ __forceinline__ float qmax(float v) {
    v = fmaxf(v, __shfl_xor_sync(0xffffffffu, v, 1));
    v = fmaxf(v, __shfl_xor_sync(0xffffffffu, v, 2));
    return v;
}
__device__ __forceinline__ float qsum(float v) {
    v += __shfl_xor_sync(0xffffffffu, v, 1);
    v += __shfl_xor_sync(0xffffffffu, v, 2);
    return v;
}

__global__ void __launch_bounds__(128, 3) attn_kernel()
{
    extern __shared__ unsigned smu[];
    unsigned* Ks = smu;                                   // [64][68]
    unsigned* Vs = Ks + 64 * KS_STRIDE;                   // [64][72]
    unsigned* Ps = Vs + 64 * VS_STRIDE;                   // [64][68]

    int tid  = threadIdx.x;
    int lane = tid & 31;
    int warp = tid >> 5;
    int g    = lane >> 2;
    int t4   = lane & 3;
    int R    = warp * 16;             // this warp's q rows within tile

    int q0 = blockIdx.x * 64;
    int h  = blockIdx.y, b = blockIdx.z;

    // Q fragments in registers (loaded once; bit-identical to old smem path)
    unsigned qfr[8][4];
    {
        const float* Qg = g_qp + ((size_t)(b * NH + h) * NQ + q0) * HDIM;
#pragma unroll
        for (int kk = 0; kk < 8; kk++) {
            int kb = kk * 8;
            qfr[kk][0] = f2tf(Qg[(R + g) * HDIM + kb + t4]);
            qfr[kk][1] = f2tf(Qg[(R + g + 8) * HDIM + kb + t4]);
            qfr[kk][2] = f2tf(Qg[(R + g) * HDIM + kb + t4 + 4]);
            qfr[kk][3] = f2tf(Qg[(R + g + 8) * HDIM + kb + t4 + 4]);
        }
    }

    float O[8][4];
    float mrow[2] = {-1e30f, -1e30f}, Z2[2] = {0.f, 0.f}, Zg2[2] = {0.f, 0.f};
#pragma unroll
    for (int nj = 0; nj < 8; nj++)
#pragma unroll
        for (int c = 0; c < 4; c++) O[nj][c] = 0.0f;

    const size_t kv_base = (size_t)(b * NH + h) * NKK * HDIM;

    for (int kbase = 0; kbase < NKK; kbase += 64) {
        __syncthreads();   // prev-tile reads done
        {
            const float* Kg = g_kp + kv_base + (size_t)kbase * HDIM;
            const float* Vg = g_vp + kv_base + (size_t)kbase * HDIM;
#pragma unroll
            for (int l = 0; l < 8; l++) {
                int idx4 = tid + l * 128;    // over 1024 float4s
                int row = idx4 >> 4, d4 = (idx4 & 15) * 4;
                float4 kv = *(const float4*)(Kg + row * HDIM + d4);
                float4 vv = *(const float4*)(Vg + row * HDIM + d4);
                *(uint4*)(&Ks[row * KS_STRIDE + d4]) =
                    make_uint4(f2tf(kv.x), f2tf(kv.y), f2tf(kv.z), f2tf(kv.w));
                *(uint4*)(&Vs[row * VS_STRIDE + d4]) =
                    make_uint4(f2tf(vv.x), f2tf(vv.y), f2tf(vv.z), f2tf(vv.w));
            }
        }
        __syncthreads();

        // ---- S = Q K^T (64x64 tile; this warp: rows R..R+15) ----
        float sfr[8][4];
#pragma unroll
        for (int nj = 0; nj < 8; nj++)
#pragma unroll
            for (int c = 0; c < 4; c++) sfr[nj][c] = 0.0f;

#pragma unroll
        for (int kk = 0; kk < 8; kk++) {
            int kb = kk * 8;
#pragma unroll
            for (int nj = 0; nj < 8; nj++) {
                unsigned bfr[2];
                bfr[0] = Ks[(nj * 8 + g) * KS_STRIDE + kb + t4];
                bfr[1] = Ks[(nj * 8 + g) * KS_STRIDE + kb + t4 + 4];
                mma_tf32(sfr[nj], qfr[kk], bfr);
            }
        }

        // ---- online softmax + gate, per half-row (rows R+g and R+g+8) ----
#pragma unroll
        for (int hf = 0; hf < 2; hf++) {
            int qrow = q0 + R + g + 8 * hf;
            const float* Gp = g_gate + ((size_t)b * NQ + qrow) * NKK + kbase;
            float Gv[16], sv[16];
            float mt = -3.0e38f;
#pragma unroll
            for (int nj = 0; nj < 8; nj++) {
                float2 gg = *(const float2*)(Gp + nj * 8 + 2 * t4);
                Gv[2 * nj] = gg.x; Gv[2 * nj + 1] = gg.y;
                float s0 = (gg.x > 0.f) ? sfr[nj][2 * hf]     : -3.0e38f;
                float s1 = (gg.y > 0.f) ? sfr[nj][2 * hf + 1] : -3.0e38f;
                sv[2 * nj] = s0; sv[2 * nj + 1] = s1;
                mt = fmaxf(mt, fmaxf(s0, s1));
            }
            mt = qmax(mt);
            float mn = fmaxf(mrow[hf], mt);
            float cs = __expf(mrow[hf] - mn);
            mrow[hf] = mn;
            float zl = 0.f, zgl = 0.f;
#pragma unroll
            for (int nj = 0; nj < 8; nj++) {
                float e0 = __expf(sv[2 * nj] - mn);
                float e1 = __expf(sv[2 * nj + 1] - mn);
                float p0 = e0 * Gv[2 * nj];
                float p1 = e1 * Gv[2 * nj + 1];
                zl += e0 + e1; zgl += p0 + p1;
                uint2 pu = make_uint2(f2tf(p0), f2tf(p1));
                *(uint2*)(&Ps[(R + g + 8 * hf) * PS_STRIDE + nj * 8 + 2 * t4]) = pu;
            }
            Z2[hf]  = Z2[hf]  * cs + zl;
            Zg2[hf] = Zg2[hf] * cs + zgl;
#pragma unroll
            for (int nj = 0; nj < 8; nj++) {
                O[nj][2 * hf]     *= cs;
                O[nj][2 * hf + 1] *= cs;
            }
        }
        __syncwarp();   // P rows are warp-private; order STS -> cross-lane LDS

        // ---- O += P @ V ----
#pragma unroll
        for (int kk = 0; kk < 8; kk++) {
            int kb = kk * 8;
            unsigned afr[4];
            afr[0] = Ps[(R + g) * PS_STRIDE + kb + t4];
            afr[1] = Ps[(R + g + 8) * PS_STRIDE + kb + t4];
            afr[2] = Ps[(R + g) * PS_STRIDE + kb + t4 + 4];
            afr[3] = Ps[(R + g + 8) * PS_STRIDE + kb + t4 + 4];
#pragma unroll
            for (int nj = 0; nj < 8; nj++) {
                unsigned bfr[2];
                bfr[0] = Vs[(kb + t4) * VS_STRIDE + nj * 8 + g];
                bfr[1] = Vs[(kb + t4 + 4) * VS_STRIDE + nj * 8 + g];
                mma_tf32(O[nj], afr, bfr);
            }
        }
    }

    // epilogue: out = O / (Zg + 1e-6*Z), write bf16 hi/lo planes directly
#pragma unroll
    for (int hf = 0; hf < 2; hf++) {
        float Zt  = qsum(Z2[hf]);
        float Zgt = qsum(Zg2[hf]);
        float inv = 1.0f / (Zgt + 1e-6f * Zt + 1e-30f);
        int qrow = q0 + R + g + 8 * hf;
        size_t obase = ((size_t)b * NQ + qrow) * (NH * HDIM) + h * HDIM;
#pragma unroll
        for (int nj = 0; nj < 8; nj++) {
            float v0 = O[nj][2 * hf] * inv;
            float v1 = O[nj][2 * hf + 1] * inv;
            __nv_bfloat16 h0 = __float2bfloat16(v0);
            __nv_bfloat16 h1 = __float2bfloat16(v1);
            __nv_bfloat16 l0 = __float2bfloat16(v0 - __bfloat162float(h0));
            __nv_bfloat16 l1 = __float2bfloat16(v1 - __bfloat162float(h1));
            size_t off = obase + nj * 8 + 2 * t4;
            *(__nv_bfloat162*)(g_ah + off) = __nv_bfloat162(h0, h1);
            *(__nv_bfloat162*)(g_al + off) = __nv_bfloat162(l0, l1);
        }
    }
}

// ---------------- launch -----------------------------------------------------
extern "C" void kernel_launch(void* const* d_in, const int* in_sizes, int n_in,
                              void* d_out, int out_size)
{
    const float* q     = (const float*)d_in[0];
    const float* k     = (const float*)d_in[1];
    const float* v     = (const float*)d_in[2];
    const float* dist  = (const float*)d_in[3];
    const void*  amask = d_in[4];
    const void*  kpmq  = d_in[5];
    const void*  kpmk  = d_in[6];
    const float* ga    = (const float*)d_in[11];
    float* out = (float*)d_out;

    const int attn_smem = ATTN_SMEM_UINTS * (int)sizeof(unsigned);  // 52 KB
    const int gemm_smem = GSMEMU * (int)sizeof(unsigned);           // 96 KB
    cudaFuncSetAttribute(attn_kernel,
                         cudaFuncAttributeMaxDynamicSharedMemorySize, attn_smem);
    cudaFuncSetAttribute(gemm_bf16x3,
                         cudaFuncAttributeMaxDynamicSharedMemorySize, gemm_smem);

    detect_kernel<<<1, 256>>>((const unsigned int*)amask);

    convert_all<<<7168, 256>>>(q, k, v,
                               (const float*)d_in[7], (const float*)d_in[8],
                               (const float*)d_in[9], (const float*)d_in[10]);

    // fused Q+K+V projection GEMMs (one launch, 640 CTAs)
    gemm_bf16x3<<<dim3(8, 80), 256, gemm_smem>>>(nullptr, -1, nullptr);

    mean_stage1<<<dim3(1024, BB), 256>>>(dist, amask, kpmk);
    mean_stage2<<<BB, 256>>>(ga);
    gate_kernel<<<(BB * NQ * NKK) / (256 * 4), 256>>>(dist, amask, kpmk);

    attn_kernel<<<dim3(NQ / 64, NH, BB), 128, attn_smem>>>();

    gemm_bf16x3<<<dim3(8, 16), 256, gemm_smem>>>(out, 3, kpmq);
}